// round 1
// baseline (speedup 1.0000x reference)
#include <cuda_runtime.h>
#include <math.h>

#define N 1024
#define TH 32
#define TW 32
#define NTHR 256

// ---- shared memory layout (in floats) ----
// W2 [16][8][4]  (k*32 + c*4 + tap), tap = di*2+dj   -> flat copy of w2
// W3 [8][16][4]  (o*64 + k*4 + tap)                  -> flat copy of w3
#define OFF_W2 0
#define OFF_W3 512
#define OFF_B2 1024
#define OFF_B3 1040
#define OFF_W4 1048
#define OFF_B4 1056
#define OFF_MS 1088                    // [34][41] mask tile (rows r0-1..r0+32)
#define OFF_M2 (OFF_MS + 34*41)        // [33][41] spread mask m2
#define OFF_H1 3840                    // [8][34][41]
#define OFF_H2 (OFF_H1 + 8*34*41)     // [16][33][41]
#define SMEM_FLOATS (OFF_H2 + 16*33*41)
#define SMEM_BYTES (SMEM_FLOATS * 4)

#define H1STR (34*41)
#define H2STR (33*41)

__device__ __forceinline__ float prelu(float x, float a) {
    return fmaxf(x, 0.f) + a * fminf(x, 0.f);
}

__global__ void __launch_bounds__(NTHR, 1)
precond_fused_kernel(const float* __restrict__ x, const int* __restrict__ mask,
                     const float* __restrict__ w1, const float* __restrict__ b1,
                     const float* __restrict__ a1p,
                     const float* __restrict__ w2, const float* __restrict__ b2,
                     const float* __restrict__ a2p,
                     const float* __restrict__ w3, const float* __restrict__ b3,
                     const float* __restrict__ a3p,
                     const float* __restrict__ w4, const float* __restrict__ b4,
                     float* __restrict__ out)
{
    extern __shared__ float sm[];
    const int tid = threadIdx.x;
    const int c0 = blockIdx.x * TW;
    const int r0 = blockIdx.y * TH;
    const int bb = blockIdx.z;

    const int rC  = tid >> 3;          // 0..31  output row within tile
    const int jj0 = (tid & 7) << 2;    // 0..28  output col group (4 wide)

    float* outB = out + (size_t)bb * N * N;

    // Tiles strictly above the diagonal are identically zero.
    if (c0 > r0 + (TH - 1)) {
        *(float4*)(outB + (size_t)(r0 + rC) * N + (c0 + jj0)) = make_float4(0.f, 0.f, 0.f, 0.f);
        return;
    }

    // ---- stage weights into shared (synced together with phase A) ----
    for (int i = tid; i < 512; i += NTHR) sm[OFF_W2 + i] = w2[i];
    for (int i = tid; i < 512; i += NTHR) sm[OFF_W3 + i] = w3[i];
    if (tid < 16) sm[OFF_B2 + tid] = b2[tid];
    if (tid < 8)  { sm[OFF_B3 + tid] = b3[tid]; sm[OFF_W4 + tid] = w4[tid]; }
    if (tid == 0) sm[OFF_B4] = b4[0];

    const float a1 = __ldg(a1p);
    const float a2 = __ldg(a2p);
    const float a3 = __ldg(a3p);

    float w1r[8], b1r[8];
    #pragma unroll
    for (int c = 0; c < 8; c++) { w1r[c] = __ldg(w1 + c); b1r[c] = __ldg(b1 + c); }

    // ---- Phase A: load x/mask halo, compute h1 (1x1 conv + PReLU) ----
    // local row lr -> image row r0-1+lr, local col lc -> image col c0-1+lc
    const float* xb = x   + (size_t)bb * N * N;
    const int*   mb = mask + (size_t)bb * N * N;
    for (int it = tid; it < 34 * 40; it += NTHR) {
        int lr = it / 40, lc = it % 40;
        int gi = r0 - 1 + lr, gj = c0 - 1 + lc;
        int   mv = 0;
        float xv = 0.f;
        if (gi >= 0 && gi < N && gj >= 0 && gj < N) {
            mv = (mb[gi * N + gj] > 0);
            if (mv) xv = xb[gi * N + gj];
        }
        sm[OFF_MS + lr * 41 + lc] = mv ? 1.f : 0.f;
        float* h1p = sm + OFF_H1 + lr * 41 + lc;
        #pragma unroll
        for (int c = 0; c < 8; c++) {
            float v = 0.f;
            if (mv) v = prelu(fmaf(w1r[c], xv, b1r[c]), a1);
            h1p[c * H1STR] = v;
        }
    }
    __syncthreads();

    // ---- Phase B: h2 = prelu(m2 * conv2(h1)) at 33 rows x 33 cols ----
    // h2 position (local r, lc): image (i' = r0+r, j' = c0-1+lc)
    // o2[i',j'] = sum_{di,dj,c} h1[i'-1+di][j'+dj] * w2[k][c][di][dj]
    // h1 local row for i'-1+di is r+di ; local col for j'+dj is lc+dj
    for (int it = tid; it < 33 * 9; it += NTHR) {
        int r = it / 9, g = it % 9;
        int lc0 = g * 4;
        int jp0 = c0 - 1 + lc0;
        float acc[4][16];
        #pragma unroll
        for (int p = 0; p < 4; p++)
            #pragma unroll
            for (int k = 0; k < 16; k++) acc[p][k] = sm[OFF_B2 + k];

        #pragma unroll 1
        for (int c = 0; c < 8; c++) {
            const float* h1c = sm + OFF_H1 + c * H1STR;
            float v0[5], v1[5];
            #pragma unroll
            for (int q = 0; q < 5; q++) {
                v0[q] = h1c[ r      * 41 + lc0 + q];
                v1[q] = h1c[(r + 1) * 41 + lc0 + q];
            }
            const float* wks = sm + OFF_W2 + c * 4;
            #pragma unroll
            for (int k = 0; k < 16; k++) {
                float w00 = wks[k * 32 + 0];
                float w01 = wks[k * 32 + 1];
                float w10 = wks[k * 32 + 2];
                float w11 = wks[k * 32 + 3];
                #pragma unroll
                for (int p = 0; p < 4; p++) {
                    acc[p][k] = fmaf(v0[p],     w00, acc[p][k]);
                    acc[p][k] = fmaf(v0[p + 1], w01, acc[p][k]);
                    acc[p][k] = fmaf(v1[p],     w10, acc[p][k]);
                    acc[p][k] = fmaf(v1[p + 1], w11, acc[p][k]);
                }
            }
        }
        float m0[5], m1[5];
        #pragma unroll
        for (int q = 0; q < 5; q++) {
            m0[q] = sm[OFF_MS +  r      * 41 + lc0 + q];
            m1[q] = sm[OFF_MS + (r + 1) * 41 + lc0 + q];
        }
        #pragma unroll
        for (int p = 0; p < 4; p++) {
            int jp = jp0 + p;
            // h2 columns outside [0, N-2] are layer-3 padding: exactly zero
            bool valid = (jp >= 0) && (jp <= N - 2);
            bool act = valid && ((m0[p] + m0[p + 1] + m1[p] + m1[p + 1]) > 0.f);
            sm[OFF_M2 + r * 41 + lc0 + p] = act ? 1.f : 0.f;
            float* h2p = sm + OFF_H2 + r * 41 + lc0 + p;
            #pragma unroll
            for (int k = 0; k < 16; k++) {
                float t = acc[p][k];
                h2p[k * H2STR] = act ? prelu(t, a2) : 0.f;
            }
        }
    }
    __syncthreads();

    // ---- Phase C: h3 = prelu(m3 * conv3(h2)); layer 4; triangular epilogue ----
    // o3[i,j] = sum_{di,dj,k} h2[i+di][j-1+dj] * w3[o][k][di][dj]
    // h2 local row = r+di, local col = (j0+p)+dj ; same windows for m3 from m2
    {
        const int r = rC, j0 = jj0;
        float acc[4][8];
        #pragma unroll
        for (int p = 0; p < 4; p++)
            #pragma unroll
            for (int o = 0; o < 8; o++) acc[p][o] = sm[OFF_B3 + o];

        #pragma unroll 1
        for (int k = 0; k < 16; k++) {
            const float* h2k = sm + OFF_H2 + k * H2STR;
            float v0[5], v1[5];
            #pragma unroll
            for (int q = 0; q < 5; q++) {
                v0[q] = h2k[ r      * 41 + j0 + q];
                v1[q] = h2k[(r + 1) * 41 + j0 + q];
            }
            const float* wos = sm + OFF_W3 + k * 4;
            #pragma unroll
            for (int o = 0; o < 8; o++) {
                float w00 = wos[o * 64 + 0];
                float w01 = wos[o * 64 + 1];
                float w10 = wos[o * 64 + 2];
                float w11 = wos[o * 64 + 3];
                #pragma unroll
                for (int p = 0; p < 4; p++) {
                    acc[p][o] = fmaf(v0[p],     w00, acc[p][o]);
                    acc[p][o] = fmaf(v0[p + 1], w01, acc[p][o]);
                    acc[p][o] = fmaf(v1[p],     w10, acc[p][o]);
                    acc[p][o] = fmaf(v1[p + 1], w11, acc[p][o]);
                }
            }
        }

        float m20[5], m21[5];
        #pragma unroll
        for (int q = 0; q < 5; q++) {
            m20[q] = sm[OFF_M2 +  r      * 41 + j0 + q];
            m21[q] = sm[OFF_M2 + (r + 1) * 41 + j0 + q];
        }
        const float b4v = sm[OFF_B4];
        const int gi = r0 + r;
        float res[4];
        #pragma unroll
        for (int p = 0; p < 4; p++) {
            bool act = (m20[p] + m20[p + 1] + m21[p] + m21[p + 1]) > 0.f;
            float o4 = b4v;
            #pragma unroll
            for (int o = 0; o < 8; o++) {
                float h3 = prelu(acc[p][o], a3);
                o4 = fmaf(sm[OFF_W4 + o], h3, o4);
            }
            o4 = act ? o4 : 0.f;
            int gj = c0 + j0 + p;
            if (gi < gj) {
                o4 = 0.f;
            } else if (gi == gj && act) {
                o4 = fmaxf(o4, 0.f) + log1pf(expf(-fabsf(o4)));  // stable softplus
            }
            res[p] = o4;
        }
        *(float4*)(outB + (size_t)gi * N + (c0 + j0)) = make_float4(res[0], res[1], res[2], res[3]);
    }
}

extern "C" void kernel_launch(void* const* d_in, const int* in_sizes, int n_in,
                              void* d_out, int out_size)
{
    (void)in_sizes; (void)n_in; (void)out_size;
    const float* x    = (const float*)d_in[0];
    const int*   mask = (const int*)  d_in[1];
    const float* w1   = (const float*)d_in[2];
    const float* b1   = (const float*)d_in[3];
    const float* a1   = (const float*)d_in[4];
    const float* w2   = (const float*)d_in[5];
    const float* b2   = (const float*)d_in[6];
    const float* a2   = (const float*)d_in[7];
    const float* w3   = (const float*)d_in[8];
    const float* b3   = (const float*)d_in[9];
    const float* a3   = (const float*)d_in[10];
    const float* w4   = (const float*)d_in[11];
    const float* b4   = (const float*)d_in[12];
    float* out = (float*)d_out;

    cudaFuncSetAttribute(precond_fused_kernel,
                         cudaFuncAttributeMaxDynamicSharedMemorySize, SMEM_BYTES);

    dim3 grid(N / TW, N / TH, 2);
    precond_fused_kernel<<<grid, NTHR, SMEM_BYTES>>>(
        x, mask, w1, b1, a1, w2, b2, a2, w3, b3, a3, w4, b4, out);
}

// round 3
// speedup vs baseline: 1.1496x; 1.1496x over previous
#include <cuda_runtime.h>
#include <math.h>

#define N 1024
#define TH 32
#define TW 32
#define NTHR 512

// ---- shared memory layout (in floats) ----
#define OFF_W2 0
#define OFF_W3 512
#define OFF_B2 1024
#define OFF_B3 1040
#define OFF_W4 1048
#define OFF_B4 1056
#define OFF_MS 1088                    // [34][41] mask tile (rows r0-1..r0+32)
#define OFF_M2 (OFF_MS + 34*41)        // [33][41] spread mask m2
#define OFF_H1 3840                    // [8][34][41]
#define OFF_H2 (OFF_H1 + 8*34*41)     // [16][33][41]
#define SMEM_FLOATS (OFF_H2 + 16*33*41)
#define SMEM_BYTES (SMEM_FLOATS * 4)

#define H1STR (34*41)
#define H2STR (33*41)

__device__ __forceinline__ float prelu(float x, float a) {
    return fmaxf(x, 0.f) + a * fminf(x, 0.f);
}

__global__ void __launch_bounds__(NTHR, 1)
precond_fused_kernel(const float* __restrict__ x, const int* __restrict__ mask,
                     const float* __restrict__ w1, const float* __restrict__ b1,
                     const float* __restrict__ a1p,
                     const float* __restrict__ w2, const float* __restrict__ b2,
                     const float* __restrict__ a2p,
                     const float* __restrict__ w3, const float* __restrict__ b3,
                     const float* __restrict__ a3p,
                     const float* __restrict__ w4, const float* __restrict__ b4,
                     float* __restrict__ out)
{
    extern __shared__ float sm[];
    const int tid = threadIdx.x;
    const int c0 = blockIdx.x * TW;
    const int r0 = blockIdx.y * TH;
    const int bb = blockIdx.z;

    const int rC  = tid >> 4;          // 0..31  output row within tile
    const int jj0 = (tid & 15) << 1;   // 0..30  output col pair

    float* outB = out + (size_t)bb * N * N;

    // Tiles strictly above the diagonal are identically zero.
    if (c0 > r0 + (TH - 1)) {
        *(float2*)(outB + (size_t)(r0 + rC) * N + (c0 + jj0)) = make_float2(0.f, 0.f);
        return;
    }

    // ---- stage weights into shared (synced together with phase A) ----
    // NTHR == 512 and both w2, w3 have exactly 512 elements: one store each.
    sm[OFF_W2 + tid] = w2[tid];
    sm[OFF_W3 + tid] = w3[tid];
    if (tid < 16) sm[OFF_B2 + tid] = b2[tid];
    if (tid < 8)  { sm[OFF_B3 + tid] = b3[tid]; sm[OFF_W4 + tid] = w4[tid]; }
    if (tid == 0) sm[OFF_B4] = b4[0];

    const float a1 = __ldg(a1p);
    const float a2 = __ldg(a2p);
    const float a3 = __ldg(a3p);

    float w1r[8], b1r[8];
    #pragma unroll
    for (int c = 0; c < 8; c++) { w1r[c] = __ldg(w1 + c); b1r[c] = __ldg(b1 + c); }

    // ---- Phase A: load x/mask halo, compute h1 (1x1 conv + PReLU) ----
    const float* xb = x    + (size_t)bb * N * N;
    const int*   mb = mask + (size_t)bb * N * N;
    for (int it = tid; it < 34 * 40; it += NTHR) {
        int lr = it / 40, lc = it % 40;
        int gi = r0 - 1 + lr, gj = c0 - 1 + lc;
        int   mv = 0;
        float xv = 0.f;
        if (gi >= 0 && gi < N && gj >= 0 && gj < N) {
            mv = (mb[gi * N + gj] > 0);
            if (mv) xv = xb[gi * N + gj];
        }
        sm[OFF_MS + lr * 41 + lc] = mv ? 1.f : 0.f;
        float* h1p = sm + OFF_H1 + lr * 41 + lc;
        #pragma unroll
        for (int c = 0; c < 8; c++) {
            float v = 0.f;
            if (mv) v = prelu(fmaf(w1r[c], xv, b1r[c]), a1);
            h1p[c * H1STR] = v;
        }
    }
    __syncthreads();

    // ---- Phase B: h2 = prelu(m2 * conv2(h1)), 33 rows x 33 cols, 3-wide groups ----
    // 33 rows x 11 groups = 363 items <= 512 threads: one pass, no ragged tail.
    if (tid < 33 * 11) {
        int r = tid / 11, g = tid % 11;
        int lc0 = g * 3;                 // 0..30, covers cols lc0..lc0+2
        int jp0 = c0 - 1 + lc0;
        float acc[3][16];
        #pragma unroll
        for (int p = 0; p < 3; p++)
            #pragma unroll
            for (int k = 0; k < 16; k++) acc[p][k] = sm[OFF_B2 + k];

        #pragma unroll 1
        for (int c = 0; c < 8; c++) {
            const float* h1c = sm + OFF_H1 + c * H1STR;
            float v0[4], v1[4];
            #pragma unroll
            for (int q = 0; q < 4; q++) {
                v0[q] = h1c[ r      * 41 + lc0 + q];
                v1[q] = h1c[(r + 1) * 41 + lc0 + q];
            }
            const float* wks = sm + OFF_W2 + c * 4;
            #pragma unroll
            for (int k = 0; k < 16; k++) {
                float w00 = wks[k * 32 + 0];
                float w01 = wks[k * 32 + 1];
                float w10 = wks[k * 32 + 2];
                float w11 = wks[k * 32 + 3];
                #pragma unroll
                for (int p = 0; p < 3; p++) {
                    acc[p][k] = fmaf(v0[p],     w00, acc[p][k]);
                    acc[p][k] = fmaf(v0[p + 1], w01, acc[p][k]);
                    acc[p][k] = fmaf(v1[p],     w10, acc[p][k]);
                    acc[p][k] = fmaf(v1[p + 1], w11, acc[p][k]);
                }
            }
        }
        float m0[4], m1[4];
        #pragma unroll
        for (int q = 0; q < 4; q++) {
            m0[q] = sm[OFF_MS +  r      * 41 + lc0 + q];
            m1[q] = sm[OFF_MS + (r + 1) * 41 + lc0 + q];
        }
        #pragma unroll
        for (int p = 0; p < 3; p++) {
            int jp = jp0 + p;
            // h2 columns outside [0, N-2] are layer-3 padding: exactly zero
            bool valid = (jp >= 0) && (jp <= N - 2);
            bool act = valid && ((m0[p] + m0[p + 1] + m1[p] + m1[p + 1]) > 0.f);
            sm[OFF_M2 + r * 41 + lc0 + p] = act ? 1.f : 0.f;
            float* h2p = sm + OFF_H2 + r * 41 + lc0 + p;
            #pragma unroll
            for (int k = 0; k < 16; k++) {
                float t = acc[p][k];
                h2p[k * H2STR] = act ? prelu(t, a2) : 0.f;
            }
        }
    }
    __syncthreads();

    // ---- Phase C: h3 = prelu(m3 * conv3(h2)); layer 4; triangular epilogue ----
    // 32 rows x 16 col-pairs = 512 items: exactly one per thread.
    {
        const int r = rC, j0 = jj0;
        float acc[2][8];
        #pragma unroll
        for (int p = 0; p < 2; p++)
            #pragma unroll
            for (int o = 0; o < 8; o++) acc[p][o] = sm[OFF_B3 + o];

        #pragma unroll 1
        for (int k = 0; k < 16; k++) {
            const float* h2k = sm + OFF_H2 + k * H2STR;
            float v0[3], v1[3];
            #pragma unroll
            for (int q = 0; q < 3; q++) {
                v0[q] = h2k[ r      * 41 + j0 + q];
                v1[q] = h2k[(r + 1) * 41 + j0 + q];
            }
            const float* wos = sm + OFF_W3 + k * 4;
            #pragma unroll
            for (int o = 0; o < 8; o++) {
                float w00 = wos[o * 64 + 0];
                float w01 = wos[o * 64 + 1];
                float w10 = wos[o * 64 + 2];
                float w11 = wos[o * 64 + 3];
                #pragma unroll
                for (int p = 0; p < 2; p++) {
                    acc[p][o] = fmaf(v0[p],     w00, acc[p][o]);
                    acc[p][o] = fmaf(v0[p + 1], w01, acc[p][o]);
                    acc[p][o] = fmaf(v1[p],     w10, acc[p][o]);
                    acc[p][o] = fmaf(v1[p + 1], w11, acc[p][o]);
                }
            }
        }

        float m20[3], m21[3];
        #pragma unroll
        for (int q = 0; q < 3; q++) {
            m20[q] = sm[OFF_M2 +  r      * 41 + j0 + q];
            m21[q] = sm[OFF_M2 + (r + 1) * 41 + j0 + q];
        }
        const float b4v = sm[OFF_B4];
        const int gi = r0 + r;
        float res[2];
        #pragma unroll
        for (int p = 0; p < 2; p++) {
            bool act = (m20[p] + m20[p + 1] + m21[p] + m21[p + 1]) > 0.f;
            float o4 = b4v;
            #pragma unroll
            for (int o = 0; o < 8; o++) {
                float h3 = prelu(acc[p][o], a3);
                o4 = fmaf(sm[OFF_W4 + o], h3, o4);
            }
            o4 = act ? o4 : 0.f;
            int gj = c0 + j0 + p;
            if (gi < gj) {
                o4 = 0.f;
            } else if (gi == gj && act) {
                o4 = fmaxf(o4, 0.f) + log1pf(expf(-fabsf(o4)));  // stable softplus
            }
            res[p] = o4;
        }
        *(float2*)(outB + (size_t)gi * N + (c0 + j0)) = make_float2(res[0], res[1]);
    }
}

extern "C" void kernel_launch(void* const* d_in, const int* in_sizes, int n_in,
                              void* d_out, int out_size)
{
    (void)in_sizes; (void)n_in; (void)out_size;
    const float* x    = (const float*)d_in[0];
    const int*   mask = (const int*)  d_in[1];
    const float* w1   = (const float*)d_in[2];
    const float* b1   = (const float*)d_in[3];
    const float* a1   = (const float*)d_in[4];
    const float* w2   = (const float*)d_in[5];
    const float* b2   = (const float*)d_in[6];
    const float* a2   = (const float*)d_in[7];
    const float* w3   = (const float*)d_in[8];
    const float* b3   = (const float*)d_in[9];
    const float* a3   = (const float*)d_in[10];
    const float* w4   = (const float*)d_in[11];
    const float* b4   = (const float*)d_in[12];
    float* out = (float*)d_out;

    cudaFuncSetAttribute(precond_fused_kernel,
                         cudaFuncAttributeMaxDynamicSharedMemorySize, SMEM_BYTES);

    dim3 grid(N / TW, N / TH, 2);
    precond_fused_kernel<<<grid, NTHR, SMEM_BYTES>>>(
        x, mask, w1, b1, a1, w2, b2, a2, w3, b3, a3, w4, b4, out);
}

// round 4
// speedup vs baseline: 1.3095x; 1.1391x over previous
#include <cuda_runtime.h>
#include <math.h>

#define N 1024
#define TH 32
#define TW 32
#define NTHR 512

// ---- shared memory layout (in floats) ----
// W2 relaid: [c][tap][k]   -> c*64 + tap*16 + k   (k-pairs contiguous)
// W3 relaid: [k][tap][o]   -> k*32 + tap*8  + o   (o-pairs contiguous)
#define OFF_W2 0
#define OFF_W3 512
#define OFF_B2 1024
#define OFF_B3 1040
#define OFF_W4 1048
#define OFF_B4 1056
#define OFF_MS 1088                    // [34][41] mask tile (rows r0-1..r0+32)
#define OFF_M2 (OFF_MS + 34*41)        // [33][41] spread mask m2
#define OFF_H1 3840                    // [8][34][41]
#define OFF_H2 (OFF_H1 + 8*34*41)     // [16][33][41]
#define SMEM_FLOATS (OFF_H2 + 16*33*41)
#define SMEM_BYTES (SMEM_FLOATS * 4)

#define H1STR (34*41)
#define H2STR (33*41)

typedef unsigned long long u64;

__device__ __forceinline__ float prelu(float x, float a) {
    return fmaxf(x, 0.f) + a * fminf(x, 0.f);
}

// pack two fp32 into a 64-bit f32x2 operand
__device__ __forceinline__ u64 pk2(float lo, float hi) {
    u64 r; asm("mov.b64 %0, {%1, %2};" : "=l"(r) : "f"(lo), "f"(hi)); return r;
}
__device__ __forceinline__ void upk2(u64 v, float& lo, float& hi) {
    asm("mov.b64 {%0, %1}, %2;" : "=f"(lo), "=f"(hi) : "l"(v));
}
// packed fp32x2 fma: d.lo=a.lo*b.lo+c.lo, d.hi=a.hi*b.hi+c.hi (exact fp32 semantics)
__device__ __forceinline__ u64 fma2(u64 a, u64 b, u64 c) {
    u64 d; asm("fma.rn.f32x2 %0, %1, %2, %3;" : "=l"(d) : "l"(a), "l"(b), "l"(c)); return d;
}
// 8B-aligned shared load of a contiguous float pair as packed operand
__device__ __forceinline__ u64 lds2(const float* p) {
    float2 t = *reinterpret_cast<const float2*>(p);
    return pk2(t.x, t.y);
}

__global__ void __launch_bounds__(NTHR, 1)
precond_fused_kernel(const float* __restrict__ x, const int* __restrict__ mask,
                     const float* __restrict__ w1, const float* __restrict__ b1,
                     const float* __restrict__ a1p,
                     const float* __restrict__ w2, const float* __restrict__ b2,
                     const float* __restrict__ a2p,
                     const float* __restrict__ w3, const float* __restrict__ b3,
                     const float* __restrict__ a3p,
                     const float* __restrict__ w4, const float* __restrict__ b4,
                     float* __restrict__ out)
{
    extern __shared__ float sm[];
    const int tid = threadIdx.x;
    const int c0 = blockIdx.x * TW;
    const int r0 = blockIdx.y * TH;
    const int bb = blockIdx.z;

    const int rC  = tid >> 4;          // 0..31  output row within tile
    const int jj0 = (tid & 15) << 1;   // 0..30  output col pair

    float* outB = out + (size_t)bb * N * N;

    // Tiles strictly above the diagonal are identically zero.
    if (c0 > r0 + (TH - 1)) {
        *(float2*)(outB + (size_t)(r0 + rC) * N + (c0 + jj0)) = make_float2(0.f, 0.f);
        return;
    }

    // ---- stage weights into shared, permuted for packed-pair access ----
    {
        // w2 input idx: k*32 + c*4 + tap  -> smem [c][tap][k]
        int k = tid >> 5, c = (tid >> 2) & 7, tap = tid & 3;
        sm[OFF_W2 + c * 64 + tap * 16 + k] = w2[tid];
        // w3 input idx: o*64 + k*4 + tap  -> smem [k][tap][o]
        int o = tid >> 6, k3 = (tid >> 2) & 15, tap3 = tid & 3;
        sm[OFF_W3 + k3 * 32 + tap3 * 8 + o] = w3[tid];
    }
    if (tid < 16) sm[OFF_B2 + tid] = b2[tid];
    if (tid < 8)  { sm[OFF_B3 + tid] = b3[tid]; sm[OFF_W4 + tid] = w4[tid]; }
    if (tid == 0) sm[OFF_B4] = b4[0];

    const float a1 = __ldg(a1p);
    const float a2 = __ldg(a2p);
    const float a3 = __ldg(a3p);

    float w1r[8], b1r[8];
    #pragma unroll
    for (int c = 0; c < 8; c++) { w1r[c] = __ldg(w1 + c); b1r[c] = __ldg(b1 + c); }

    // ---- Phase A: load x/mask halo, compute h1 (1x1 conv + PReLU) ----
    const float* xb = x    + (size_t)bb * N * N;
    const int*   mb = mask + (size_t)bb * N * N;
    for (int it = tid; it < 34 * 40; it += NTHR) {
        int lr = it / 40, lc = it % 40;
        int gi = r0 - 1 + lr, gj = c0 - 1 + lc;
        int   mv = 0;
        float xv = 0.f;
        if (gi >= 0 && gi < N && gj >= 0 && gj < N) {
            mv = (mb[gi * N + gj] > 0);
            if (mv) xv = xb[gi * N + gj];
        }
        sm[OFF_MS + lr * 41 + lc] = mv ? 1.f : 0.f;
        float* h1p = sm + OFF_H1 + lr * 41 + lc;
        #pragma unroll
        for (int c = 0; c < 8; c++) {
            float v = 0.f;
            if (mv) v = prelu(fmaf(w1r[c], xv, b1r[c]), a1);
            h1p[c * H1STR] = v;
        }
    }
    __syncthreads();

    // ---- Phase B: h2 = prelu(m2 * conv2(h1)), packed k-pairs ----
    // 33 rows x 11 groups (width 3) = 363 items, one per thread.
    if (tid < 33 * 11) {
        int r = tid / 11, g = tid % 11;
        int lc0 = g * 3;                 // 0..30
        int jp0 = c0 - 1 + lc0;
        u64 acc2[3][8];                  // [p][k-pair]
        #pragma unroll
        for (int k2 = 0; k2 < 8; k2++) {
            u64 bpair = lds2(sm + OFF_B2 + 2 * k2);
            #pragma unroll
            for (int p = 0; p < 3; p++) acc2[p][k2] = bpair;
        }

        #pragma unroll 1
        for (int c = 0; c < 8; c++) {
            const float* h1c = sm + OFF_H1 + c * H1STR;
            u64 vv0[4], vv1[4];
            #pragma unroll
            for (int q = 0; q < 4; q++) {
                float t0 = h1c[ r      * 41 + lc0 + q];
                float t1 = h1c[(r + 1) * 41 + lc0 + q];
                vv0[q] = pk2(t0, t0);
                vv1[q] = pk2(t1, t1);
            }
            const float* wc = sm + OFF_W2 + c * 64;
            #pragma unroll
            for (int k2 = 0; k2 < 8; k2++) {
                u64 w00 = lds2(wc +  0 + 2 * k2);
                u64 w01 = lds2(wc + 16 + 2 * k2);
                u64 w10 = lds2(wc + 32 + 2 * k2);
                u64 w11 = lds2(wc + 48 + 2 * k2);
                #pragma unroll
                for (int p = 0; p < 3; p++) {
                    acc2[p][k2] = fma2(vv0[p],     w00, acc2[p][k2]);
                    acc2[p][k2] = fma2(vv0[p + 1], w01, acc2[p][k2]);
                    acc2[p][k2] = fma2(vv1[p],     w10, acc2[p][k2]);
                    acc2[p][k2] = fma2(vv1[p + 1], w11, acc2[p][k2]);
                }
            }
        }
        float m0[4], m1[4];
        #pragma unroll
        for (int q = 0; q < 4; q++) {
            m0[q] = sm[OFF_MS +  r      * 41 + lc0 + q];
            m1[q] = sm[OFF_MS + (r + 1) * 41 + lc0 + q];
        }
        #pragma unroll
        for (int p = 0; p < 3; p++) {
            int jp = jp0 + p;
            // h2 columns outside [0, N-2] are layer-3 padding: exactly zero
            bool valid = (jp >= 0) && (jp <= N - 2);
            bool act = valid && ((m0[p] + m0[p + 1] + m1[p] + m1[p + 1]) > 0.f);
            sm[OFF_M2 + r * 41 + lc0 + p] = act ? 1.f : 0.f;
            float* h2p = sm + OFF_H2 + r * 41 + lc0 + p;
            #pragma unroll
            for (int k2 = 0; k2 < 8; k2++) {
                float t0, t1;
                upk2(acc2[p][k2], t0, t1);
                h2p[(2 * k2)     * H2STR] = act ? prelu(t0, a2) : 0.f;
                h2p[(2 * k2 + 1) * H2STR] = act ? prelu(t1, a2) : 0.f;
            }
        }
    }
    __syncthreads();

    // ---- Phase C: h3 = prelu(m3 * conv3(h2)); layer 4; packed o-pairs ----
    // 32 rows x 16 col-pairs = 512 items: exactly one per thread.
    {
        const int r = rC, j0 = jj0;
        u64 acc2[2][4];                  // [p][o-pair]
        #pragma unroll
        for (int o2 = 0; o2 < 4; o2++) {
            u64 bpair = lds2(sm + OFF_B3 + 2 * o2);
            acc2[0][o2] = bpair;
            acc2[1][o2] = bpair;
        }

        #pragma unroll 1
        for (int k = 0; k < 16; k++) {
            const float* h2k = sm + OFF_H2 + k * H2STR;
            u64 vv0[3], vv1[3];
            #pragma unroll
            for (int q = 0; q < 3; q++) {
                float t0 = h2k[ r      * 41 + j0 + q];
                float t1 = h2k[(r + 1) * 41 + j0 + q];
                vv0[q] = pk2(t0, t0);
                vv1[q] = pk2(t1, t1);
            }
            const float* wk = sm + OFF_W3 + k * 32;
            #pragma unroll
            for (int o2 = 0; o2 < 4; o2++) {
                u64 w00 = lds2(wk +  0 + 2 * o2);
                u64 w01 = lds2(wk +  8 + 2 * o2);
                u64 w10 = lds2(wk + 16 + 2 * o2);
                u64 w11 = lds2(wk + 24 + 2 * o2);
                #pragma unroll
                for (int p = 0; p < 2; p++) {
                    acc2[p][o2] = fma2(vv0[p],     w00, acc2[p][o2]);
                    acc2[p][o2] = fma2(vv0[p + 1], w01, acc2[p][o2]);
                    acc2[p][o2] = fma2(vv1[p],     w10, acc2[p][o2]);
                    acc2[p][o2] = fma2(vv1[p + 1], w11, acc2[p][o2]);
                }
            }
        }

        float m20[3], m21[3];
        #pragma unroll
        for (int q = 0; q < 3; q++) {
            m20[q] = sm[OFF_M2 +  r      * 41 + j0 + q];
            m21[q] = sm[OFF_M2 + (r + 1) * 41 + j0 + q];
        }
        const float b4v = sm[OFF_B4];
        const int gi = r0 + r;
        float res[2];
        #pragma unroll
        for (int p = 0; p < 2; p++) {
            bool act = (m20[p] + m20[p + 1] + m21[p] + m21[p + 1]) > 0.f;
            float o4 = b4v;
            #pragma unroll
            for (int o2 = 0; o2 < 4; o2++) {
                float h3a, h3b;
                upk2(acc2[p][o2], h3a, h3b);
                o4 = fmaf(sm[OFF_W4 + 2 * o2],     prelu(h3a, a3), o4);
                o4 = fmaf(sm[OFF_W4 + 2 * o2 + 1], prelu(h3b, a3), o4);
            }
            o4 = act ? o4 : 0.f;
            int gj = c0 + j0 + p;
            if (gi < gj) {
                o4 = 0.f;
            } else if (gi == gj && act) {
                o4 = fmaxf(o4, 0.f) + log1pf(expf(-fabsf(o4)));  // stable softplus
            }
            res[p] = o4;
        }
        *(float2*)(outB + (size_t)gi * N + (c0 + j0)) = make_float2(res[0], res[1]);
    }
}

extern "C" void kernel_launch(void* const* d_in, const int* in_sizes, int n_in,
                              void* d_out, int out_size)
{
    (void)in_sizes; (void)n_in; (void)out_size;
    const float* x    = (const float*)d_in[0];
    const int*   mask = (const int*)  d_in[1];
    const float* w1   = (const float*)d_in[2];
    const float* b1   = (const float*)d_in[3];
    const float* a1   = (const float*)d_in[4];
    const float* w2   = (const float*)d_in[5];
    const float* b2   = (const float*)d_in[6];
    const float* a2   = (const float*)d_in[7];
    const float* w3   = (const float*)d_in[8];
    const float* b3   = (const float*)d_in[9];
    const float* a3   = (const float*)d_in[10];
    const float* w4   = (const float*)d_in[11];
    const float* b4   = (const float*)d_in[12];
    float* out = (float*)d_out;

    cudaFuncSetAttribute(precond_fused_kernel,
                         cudaFuncAttributeMaxDynamicSharedMemorySize, SMEM_BYTES);

    dim3 grid(N / TW, N / TH, 2);
    precond_fused_kernel<<<grid, NTHR, SMEM_BYTES>>>(
        x, mask, w1, b1, a1, w2, b2, a2, w3, b3, a3, w4, b4, out);
}

// round 5
// speedup vs baseline: 1.4016x; 1.0704x over previous
#include <cuda_runtime.h>
#include <math.h>

#define N 1024
#define TH 32
#define TW 16
#define NTHR 256

// ---- shared memory layout (in floats) ----
// W2 relaid: [c][tap][k]   -> c*64 + tap*16 + k   (k-pairs contiguous)
// W3 relaid: [k][tap][o]   -> k*32 + tap*8  + o   (o-pairs contiguous)
#define OFF_W2 0
#define OFF_W3 512
#define OFF_B2 1024
#define OFF_B3 1040
#define OFF_W4 1048
#define OFF_B4 1056
#define OFF_W1 1064
#define OFF_B1 1072
#define OFF_XM 1088                    // [34][19] masked x (rows r0-1..r0+32, cols c0-1..c0+17)
#define OFF_MS (OFF_XM + 34*19)       // [34][19] mask
#define OFF_M2 (OFF_MS + 34*19)       // [33][19] spread mask m2
#define OFF_H2 3008                    // [16][33][19]
#define SMEM_FLOATS (OFF_H2 + 16*33*19)
#define SMEM_BYTES (SMEM_FLOATS * 4)

#define H2STR (33*19)
#define LSTR 19

typedef unsigned long long u64;

__device__ __forceinline__ float prelu(float x, float a) {
    return fmaxf(x, 0.f) + a * fminf(x, 0.f);
}

__device__ __forceinline__ u64 pk2(float lo, float hi) {
    u64 r; asm("mov.b64 %0, {%1, %2};" : "=l"(r) : "f"(lo), "f"(hi)); return r;
}
__device__ __forceinline__ void upk2(u64 v, float& lo, float& hi) {
    asm("mov.b64 {%0, %1}, %2;" : "=f"(lo), "=f"(hi) : "l"(v));
}
__device__ __forceinline__ u64 fma2(u64 a, u64 b, u64 c) {
    u64 d; asm("fma.rn.f32x2 %0, %1, %2, %3;" : "=l"(d) : "l"(a), "l"(b), "l"(c)); return d;
}
__device__ __forceinline__ u64 lds2(const float* p) {
    float2 t = *reinterpret_cast<const float2*>(p);
    return pk2(t.x, t.y);
}

__global__ void __launch_bounds__(NTHR, 2)
precond_fused_kernel(const float* __restrict__ x, const int* __restrict__ mask,
                     const float* __restrict__ w1, const float* __restrict__ b1,
                     const float* __restrict__ a1p,
                     const float* __restrict__ w2, const float* __restrict__ b2,
                     const float* __restrict__ a2p,
                     const float* __restrict__ w3, const float* __restrict__ b3,
                     const float* __restrict__ a3p,
                     const float* __restrict__ w4, const float* __restrict__ b4,
                     float* __restrict__ out)
{
    extern __shared__ float sm[];
    const int tid = threadIdx.x;
    const int c0 = blockIdx.x * TW;
    const int r0 = blockIdx.y * TH;
    const int bb = blockIdx.z;

    const int rC  = tid & 31;          // 0..31 output row (consecutive lanes -> rows)
    const int jj0 = (tid >> 5) << 1;   // 0..14 output col pair

    float* outB = out + (size_t)bb * N * N;

    // Tiles strictly above the diagonal are identically zero.
    if (c0 > r0 + (TH - 1)) {
        *(float2*)(outB + (size_t)(r0 + rC) * N + (c0 + jj0)) = make_float2(0.f, 0.f);
        return;
    }

    // ---- stage weights into shared, permuted for packed-pair access ----
    #pragma unroll
    for (int i = tid; i < 512; i += NTHR) {
        // w2 input idx: k*32 + c*4 + tap  -> smem [c][tap][k]
        int k = i >> 5, c = (i >> 2) & 7, tap = i & 3;
        sm[OFF_W2 + c * 64 + tap * 16 + k] = w2[i];
        // w3 input idx: o*64 + k*4 + tap  -> smem [k][tap][o]
        int o = i >> 6, k3 = (i >> 2) & 15, tap3 = i & 3;
        sm[OFF_W3 + k3 * 32 + tap3 * 8 + o] = w3[i];
    }
    if (tid < 16) sm[OFF_B2 + tid] = b2[tid];
    if (tid < 8)  {
        sm[OFF_B3 + tid] = b3[tid];
        sm[OFF_W4 + tid] = w4[tid];
        sm[OFF_W1 + tid] = w1[tid];
        sm[OFF_B1 + tid] = b1[tid];
    }
    if (tid == 0) sm[OFF_B4] = b4[0];

    const float a1 = __ldg(a1p);
    const float a2 = __ldg(a2p);
    const float a3 = __ldg(a3p);

    // ---- Phase A: load masked x + mask halo (34 rows x 19 cols) ----
    const float* xb = x    + (size_t)bb * N * N;
    const int*   mb = mask + (size_t)bb * N * N;
    for (int it = tid; it < 34 * 19; it += NTHR) {
        int lr = it / 19, lc = it % 19;
        int gi = r0 - 1 + lr, gj = c0 - 1 + lc;
        int   mv = 0;
        float xv = 0.f;
        if (gi >= 0 && gi < N && gj >= 0 && gj < N) {
            mv = (mb[gi * N + gj] > 0);
            if (mv) xv = xb[gi * N + gj];
        }
        sm[OFF_MS + it] = mv ? 1.f : 0.f;
        sm[OFF_XM + it] = xv;
    }
    __syncthreads();

    // ---- Phase B: h2 = prelu(m2 * conv2(h1)), h1 recomputed on the fly ----
    // 33 rows x 6 groups (width 3, covering 18 >= 17 needed cols) = 198 items.
    if (tid < 33 * 6) {
        int r = tid % 33, g = tid / 33;       // consecutive lanes -> consecutive rows
        int lc0 = g * 3;                       // 0,3,..,15
        int jp0 = c0 - 1 + lc0;
        // load masked x + mask windows once (16 LDS, conflict-free: row-stride 19)
        float x0[4], x1[4], s0[4], s1[4];
        #pragma unroll
        for (int q = 0; q < 4; q++) {
            x0[q] = sm[OFF_XM +  r      * LSTR + lc0 + q];
            x1[q] = sm[OFF_XM + (r + 1) * LSTR + lc0 + q];
            s0[q] = sm[OFF_MS +  r      * LSTR + lc0 + q];
            s1[q] = sm[OFF_MS + (r + 1) * LSTR + lc0 + q];
        }

        u64 acc2[3][8];                  // [p][k-pair]
        #pragma unroll
        for (int k2 = 0; k2 < 8; k2++) {
            u64 bpair = lds2(sm + OFF_B2 + 2 * k2);
            #pragma unroll
            for (int p = 0; p < 3; p++) acc2[p][k2] = bpair;
        }

        #pragma unroll 1
        for (int c = 0; c < 8; c++) {
            const float w1c = sm[OFF_W1 + c];
            const float b1c = sm[OFF_B1 + c];
            u64 vv0[4], vv1[4];
            #pragma unroll
            for (int q = 0; q < 4; q++) {
                float t0 = s0[q] * prelu(fmaf(w1c, x0[q], b1c), a1);
                float t1 = s1[q] * prelu(fmaf(w1c, x1[q], b1c), a1);
                vv0[q] = pk2(t0, t0);
                vv1[q] = pk2(t1, t1);
            }
            const float* wc = sm + OFF_W2 + c * 64;
            #pragma unroll
            for (int k2 = 0; k2 < 8; k2++) {
                u64 w00 = lds2(wc +  0 + 2 * k2);
                u64 w01 = lds2(wc + 16 + 2 * k2);
                u64 w10 = lds2(wc + 32 + 2 * k2);
                u64 w11 = lds2(wc + 48 + 2 * k2);
                #pragma unroll
                for (int p = 0; p < 3; p++) {
                    acc2[p][k2] = fma2(vv0[p],     w00, acc2[p][k2]);
                    acc2[p][k2] = fma2(vv0[p + 1], w01, acc2[p][k2]);
                    acc2[p][k2] = fma2(vv1[p],     w10, acc2[p][k2]);
                    acc2[p][k2] = fma2(vv1[p + 1], w11, acc2[p][k2]);
                }
            }
        }
        #pragma unroll
        for (int p = 0; p < 3; p++) {
            int jp = jp0 + p;
            // h2 columns outside [0, N-2] are layer-3 padding: exactly zero
            bool valid = (jp >= 0) && (jp <= N - 2);
            bool act = valid && ((s0[p] + s0[p + 1] + s1[p] + s1[p + 1]) > 0.f);
            sm[OFF_M2 + r * LSTR + lc0 + p] = act ? 1.f : 0.f;
            float* h2p = sm + OFF_H2 + r * LSTR + lc0 + p;
            #pragma unroll
            for (int k2 = 0; k2 < 8; k2++) {
                float t0, t1;
                upk2(acc2[p][k2], t0, t1);
                h2p[(2 * k2)     * H2STR] = act ? prelu(t0, a2) : 0.f;
                h2p[(2 * k2 + 1) * H2STR] = act ? prelu(t1, a2) : 0.f;
            }
        }
    }
    __syncthreads();

    // ---- Phase C: h3 = prelu(m3 * conv3(h2)); layer 4; packed o-pairs ----
    // 32 rows x 8 col-pairs = 256 items: exactly one per thread.
    {
        const int r = rC, j0 = jj0;
        u64 acc2[2][4];                  // [p][o-pair]
        #pragma unroll
        for (int o2 = 0; o2 < 4; o2++) {
            u64 bpair = lds2(sm + OFF_B3 + 2 * o2);
            acc2[0][o2] = bpair;
            acc2[1][o2] = bpair;
        }

        #pragma unroll 1
        for (int k = 0; k < 16; k++) {
            const float* h2k = sm + OFF_H2 + k * H2STR;
            u64 vv0[3], vv1[3];
            #pragma unroll
            for (int q = 0; q < 3; q++) {
                float t0 = h2k[ r      * LSTR + j0 + q];
                float t1 = h2k[(r + 1) * LSTR + j0 + q];
                vv0[q] = pk2(t0, t0);
                vv1[q] = pk2(t1, t1);
            }
            const float* wk = sm + OFF_W3 + k * 32;
            #pragma unroll
            for (int o2 = 0; o2 < 4; o2++) {
                u64 w00 = lds2(wk +  0 + 2 * o2);
                u64 w01 = lds2(wk +  8 + 2 * o2);
                u64 w10 = lds2(wk + 16 + 2 * o2);
                u64 w11 = lds2(wk + 24 + 2 * o2);
                #pragma unroll
                for (int p = 0; p < 2; p++) {
                    acc2[p][o2] = fma2(vv0[p],     w00, acc2[p][o2]);
                    acc2[p][o2] = fma2(vv0[p + 1], w01, acc2[p][o2]);
                    acc2[p][o2] = fma2(vv1[p],     w10, acc2[p][o2]);
                    acc2[p][o2] = fma2(vv1[p + 1], w11, acc2[p][o2]);
                }
            }
        }

        float m20[3], m21[3];
        #pragma unroll
        for (int q = 0; q < 3; q++) {
            m20[q] = sm[OFF_M2 +  r      * LSTR + j0 + q];
            m21[q] = sm[OFF_M2 + (r + 1) * LSTR + j0 + q];
        }
        const float b4v = sm[OFF_B4];
        const int gi = r0 + r;
        float res[2];
        #pragma unroll
        for (int p = 0; p < 2; p++) {
            bool act = (m20[p] + m20[p + 1] + m21[p] + m21[p + 1]) > 0.f;
            float o4 = b4v;
            #pragma unroll
            for (int o2 = 0; o2 < 4; o2++) {
                float h3a, h3b;
                upk2(acc2[p][o2], h3a, h3b);
                o4 = fmaf(sm[OFF_W4 + 2 * o2],     prelu(h3a, a3), o4);
                o4 = fmaf(sm[OFF_W4 + 2 * o2 + 1], prelu(h3b, a3), o4);
            }
            o4 = act ? o4 : 0.f;
            int gj = c0 + j0 + p;
            if (gi < gj) {
                o4 = 0.f;
            } else if (gi == gj && act) {
                o4 = fmaxf(o4, 0.f) + log1pf(expf(-fabsf(o4)));  // stable softplus
            }
            res[p] = o4;
        }
        *(float2*)(outB + (size_t)gi * N + (c0 + j0)) = make_float2(res[0], res[1]);
    }
}

extern "C" void kernel_launch(void* const* d_in, const int* in_sizes, int n_in,
                              void* d_out, int out_size)
{
    (void)in_sizes; (void)n_in; (void)out_size;
    const float* x    = (const float*)d_in[0];
    const int*   mask = (const int*)  d_in[1];
    const float* w1   = (const float*)d_in[2];
    const float* b1   = (const float*)d_in[3];
    const float* a1   = (const float*)d_in[4];
    const float* w2   = (const float*)d_in[5];
    const float* b2   = (const float*)d_in[6];
    const float* a2   = (const float*)d_in[7];
    const float* w3   = (const float*)d_in[8];
    const float* b3   = (const float*)d_in[9];
    const float* a3   = (const float*)d_in[10];
    const float* w4   = (const float*)d_in[11];
    const float* b4   = (const float*)d_in[12];
    float* out = (float*)d_out;

    cudaFuncSetAttribute(precond_fused_kernel,
                         cudaFuncAttributeMaxDynamicSharedMemorySize, SMEM_BYTES);

    dim3 grid(N / TW, N / TH, 2);
    precond_fused_kernel<<<grid, NTHR, SMEM_BYTES>>>(
        x, mask, w1, b1, a1, w2, b2, a2, w3, b3, a3, w4, b4, out);
}